// round 10
// baseline (speedup 1.0000x reference)
#include <cuda_runtime.h>
#include <cuda_bf16.h>
#include <math.h>
#include <cstdint>

#define N_NODES 100000
#define D 128
#define D_LAT 64
#define N_EDGES 1600000
#define SCAN_BLOCKS ((N_NODES + 255) / 256)   // 391

// Scratch (device globals: allocation-free, graph-capture safe)
__device__ __nv_bfloat16  g_aggr[(size_t)N_NODES * D];
__device__ __nv_bfloat16  g_hA[(size_t)N_NODES * D];
__device__ __nv_bfloat16  g_hB[(size_t)N_NODES * D];
__device__ float g_pool[D];
__device__ int   g_deg[N_NODES];
__device__ int   g_offs[N_NODES];
__device__ int   g_cursor[N_NODES];
__device__ int   g_part[SCAN_BLOCKS];
__device__ int   g_perm[N_EDGES];
// transposed weights, bf16 hi/lo split: [mat 0..5][n*128+k]
__device__ __nv_bfloat16 g_wh[6 * 128 * 128];
__device__ __nv_bfloat16 g_wl[6 * 128 * 128];

// ===========================================================================
__device__ __forceinline__ float4 bf4_to_f4(uint2 u) {
    __nv_bfloat162 a = *reinterpret_cast<__nv_bfloat162*>(&u.x);
    __nv_bfloat162 b = *reinterpret_cast<__nv_bfloat162*>(&u.y);
    float2 fa = __bfloat1622float2(a);
    float2 fb = __bfloat1622float2(b);
    return make_float4(fa.x, fa.y, fb.x, fb.y);
}
__device__ __forceinline__ uint32_t pack_bf16(float a, float b) {
    __nv_bfloat16 ha = __float2bfloat16(a);
    __nv_bfloat16 hb = __float2bfloat16(b);
    return (uint32_t)__bfloat16_as_ushort(ha) |
           ((uint32_t)__bfloat16_as_ushort(hb) << 16);
}

// ===========================================================================
// small utility kernels
// ===========================================================================
__global__ void zero_i_kernel(int* __restrict__ p, int n) {
    int i = blockIdx.x * blockDim.x + threadIdx.x;
    if (i < n) p[i] = 0;
}
__global__ void zero_f_kernel(float* __restrict__ p, int n) {
    int i = blockIdx.x * blockDim.x + threadIdx.x;
    if (i < n) p[i] = 0.f;
}
__global__ void count_kernel(const int* __restrict__ dst, int* __restrict__ deg) {
    int e = blockIdx.x * blockDim.x + threadIdx.x;
    if (e < N_EDGES) atomicAdd(&deg[dst[e]], 1);
}
__global__ void scan1_kernel(const int* __restrict__ deg,
                             int* __restrict__ offs, int* __restrict__ part) {
    __shared__ int s[256];
    int t = threadIdx.x;
    int i = blockIdx.x * 256 + t;
    int v = (i < N_NODES) ? deg[i] : 0;
    s[t] = v;
    __syncthreads();
#pragma unroll
    for (int d = 1; d < 256; d <<= 1) {
        int u = (t >= d) ? s[t - d] : 0;
        __syncthreads();
        s[t] += u;
        __syncthreads();
    }
    if (i < N_NODES) offs[i] = s[t] - v;
    if (t == 255) part[blockIdx.x] = s[255];
}
__global__ void scan2_kernel(int* __restrict__ part) {
    __shared__ int s[512];
    int t = threadIdx.x;
    int v = (t < SCAN_BLOCKS) ? part[t] : 0;
    s[t] = v;
    __syncthreads();
#pragma unroll
    for (int d = 1; d < 512; d <<= 1) {
        int u = (t >= d) ? s[t - d] : 0;
        __syncthreads();
        s[t] += u;
        __syncthreads();
    }
    if (t < SCAN_BLOCKS) part[t] = s[t] - v;
}
__global__ void scan3_kernel(int* __restrict__ offs, const int* __restrict__ part,
                             int* __restrict__ cursor) {
    int i = blockIdx.x * blockDim.x + threadIdx.x;
    if (i < N_NODES) {
        int o = offs[i] + part[i >> 8];
        offs[i] = o;
        cursor[i] = o;
    }
}
__global__ void permute_kernel(const int* __restrict__ src, const int* __restrict__ dst,
                               int* __restrict__ cursor, int* __restrict__ perm) {
    int e = blockIdx.x * blockDim.x + threadIdx.x;
    if (e < N_EDGES) {
        int pos = atomicAdd(&cursor[dst[e]], 1);
        perm[pos] = src[e];
    }
}
__global__ void prep_w6_kernel(const float* __restrict__ W0, const float* __restrict__ W1,
                               const float* __restrict__ W2, const float* __restrict__ W3,
                               const float* __restrict__ W4, const float* __restrict__ W5,
                               __nv_bfloat16* __restrict__ Th,
                               __nv_bfloat16* __restrict__ Tl) {
    int t = blockIdx.x * 256 + threadIdx.x;
    if (t >= 6 * 16384) return;
    int m = t >> 14, i = t & 16383;
    const float* W = (m == 0) ? W0 : (m == 1) ? W1 : (m == 2) ? W2
                   : (m == 3) ? W3 : (m == 4) ? W4 : W5;
    int n = i >> 7, k = i & 127;
    float w = W[k * 128 + n];
    __nv_bfloat16 h = __float2bfloat16(w);
    Th[t] = h;
    Tl[t] = __float2bfloat16(w - __bfloat162float(h));
}

// ===========================================================================
// gather-based mean aggregation: one warp per node, unroll 8 (MLP 8):
// all 8 perm loads issued first (independent), then 8 feature loads.
// Output stored bf16 (A-side rounding is random; cancels in pool).
// ===========================================================================
template<bool BF16IN>
__global__ __launch_bounds__(256) void gather_aggr_t(
    const void* __restrict__ xv, const int* __restrict__ perm,
    const int* __restrict__ offs, const int* __restrict__ deg,
    __nv_bfloat16* __restrict__ aggr)
{
    int warp = (blockIdx.x * blockDim.x + threadIdx.x) >> 5;
    int lane = threadIdx.x & 31;
    if (warp >= N_NODES) return;
    int beg = __ldg(&offs[warp]);
    int cnt = __ldg(&deg[warp]);
    int end = beg + cnt;

    const uint2*  x2 = (const uint2*)xv;
    const float4* x4 = (const float4*)xv;

    float4 acc = make_float4(0.f, 0.f, 0.f, 0.f);
    int e = beg;
    for (; e + 8 <= end; e += 8) {
        int s0 = __ldg(&perm[e + 0]);
        int s1 = __ldg(&perm[e + 1]);
        int s2 = __ldg(&perm[e + 2]);
        int s3 = __ldg(&perm[e + 3]);
        int s4 = __ldg(&perm[e + 4]);
        int s5 = __ldg(&perm[e + 5]);
        int s6 = __ldg(&perm[e + 6]);
        int s7 = __ldg(&perm[e + 7]);
        float4 v0, v1, v2, v3, v4, v5, v6, v7;
        if (BF16IN) {
            v0 = bf4_to_f4(__ldg(x2 + (size_t)s0 * 32 + lane));
            v1 = bf4_to_f4(__ldg(x2 + (size_t)s1 * 32 + lane));
            v2 = bf4_to_f4(__ldg(x2 + (size_t)s2 * 32 + lane));
            v3 = bf4_to_f4(__ldg(x2 + (size_t)s3 * 32 + lane));
            v4 = bf4_to_f4(__ldg(x2 + (size_t)s4 * 32 + lane));
            v5 = bf4_to_f4(__ldg(x2 + (size_t)s5 * 32 + lane));
            v6 = bf4_to_f4(__ldg(x2 + (size_t)s6 * 32 + lane));
            v7 = bf4_to_f4(__ldg(x2 + (size_t)s7 * 32 + lane));
        } else {
            v0 = __ldg(x4 + (size_t)s0 * 32 + lane);
            v1 = __ldg(x4 + (size_t)s1 * 32 + lane);
            v2 = __ldg(x4 + (size_t)s2 * 32 + lane);
            v3 = __ldg(x4 + (size_t)s3 * 32 + lane);
            v4 = __ldg(x4 + (size_t)s4 * 32 + lane);
            v5 = __ldg(x4 + (size_t)s5 * 32 + lane);
            v6 = __ldg(x4 + (size_t)s6 * 32 + lane);
            v7 = __ldg(x4 + (size_t)s7 * 32 + lane);
        }
        acc.x += ((v0.x + v1.x) + (v2.x + v3.x)) + ((v4.x + v5.x) + (v6.x + v7.x));
        acc.y += ((v0.y + v1.y) + (v2.y + v3.y)) + ((v4.y + v5.y) + (v6.y + v7.y));
        acc.z += ((v0.z + v1.z) + (v2.z + v3.z)) + ((v4.z + v5.z) + (v6.z + v7.z));
        acc.w += ((v0.w + v1.w) + (v2.w + v3.w)) + ((v4.w + v5.w) + (v6.w + v7.w));
    }
    for (; e < end; e++) {
        int s0 = __ldg(&perm[e]);
        float4 v0 = BF16IN ? bf4_to_f4(__ldg(x2 + (size_t)s0 * 32 + lane))
                           : __ldg(x4 + (size_t)s0 * 32 + lane);
        acc.x += v0.x; acc.y += v0.y; acc.z += v0.z; acc.w += v0.w;
    }
    float sc = (cnt > 0) ? (1.0f / (float)cnt) : 0.0f;
    uint2 o;
    o.x = pack_bf16(acc.x * sc, acc.y * sc);
    o.y = pack_bf16(acc.z * sc, acc.w * sc);
    ((uint2*)aggr)[(size_t)warp * 32 + lane] = o;
}

// ===========================================================================
// bf16 mma.sync fused SAGE layer:
//   out_bf16 = relu( aggr @ Wl + xin @ Wr + b )
// A-side single bf16 (2 MMAs vs W hi/lo); fp32 xin (layer 1) gets hi/lo
// split (3 MMAs). W always hi/lo. CTA 128x128, warp 64x32, K=256 in 8x32.
// ===========================================================================
#define A_STRIDE 80   // 16B-aligned; bank = (grp*20 + tig) mod 32 -> conflict-free
#define TILE_BYTES (128 * A_STRIDE)  // 10240

__device__ __forceinline__ void mma_bf16(float* c, const uint32_t* a,
                                         uint32_t b0, uint32_t b1) {
    asm volatile(
        "mma.sync.aligned.m16n8k16.row.col.f32.bf16.bf16.f32 "
        "{%0,%1,%2,%3}, {%4,%5,%6,%7}, {%8,%9}, {%0,%1,%2,%3};\n"
        : "+f"(c[0]), "+f"(c[1]), "+f"(c[2]), "+f"(c[3])
        : "r"(a[0]), "r"(a[1]), "r"(a[2]), "r"(a[3]), "r"(b0), "r"(b1));
}

template<bool BF16IN>
__global__ __launch_bounds__(256, 2) void sage_gemm_mma_t(
    const __nv_bfloat16* __restrict__ aggr, const void* __restrict__ xin,
    const __nv_bfloat16* __restrict__ WlTh, const __nv_bfloat16* __restrict__ WlTl,
    const __nv_bfloat16* __restrict__ WrTh, const __nv_bfloat16* __restrict__ WrTl,
    const float* __restrict__ bias, __nv_bfloat16* __restrict__ out)
{
    __shared__ char sAh[TILE_BYTES];
    __shared__ char sAl[TILE_BYTES];   // only used for fp32 xin (layer 1)
    __shared__ char sWh[TILE_BYTES];
    __shared__ char sWl[TILE_BYTES];

    const int t    = threadIdx.x;
    const int wid  = t >> 5;
    const int lane = t & 31;
    const int grp  = lane >> 2;
    const int tig  = lane & 3;
    const int warpM = wid >> 2;
    const int warpN = wid & 3;
    const int m0 = blockIdx.x * 128;

    float acc[4][4][4];
#pragma unroll
    for (int i = 0; i < 4; i++)
#pragma unroll
        for (int j = 0; j < 4; j++)
#pragma unroll
            for (int r = 0; r < 4; r++) acc[i][j][r] = 0.f;

    const int arow  = t >> 1;
    const int ahalf = t & 1;
    const int gr = m0 + arow;

    for (int c = 0; c < 8; c++) {
        const bool fh = (c < 4);          // aggregation half of K
        const int k0 = (c & 3) * 32;
        const bool useAl = !fh && !BF16IN;

        // ---- load A chunk: rows 128 x 32 k
        if (fh || BF16IN) {
            const __nv_bfloat16* srcb = fh ? aggr : (const __nv_bfloat16*)xin;
            const uint4* srcp = (const uint4*)(srcb + (size_t)gr * 128 + k0 + ahalf * 16);
            uint4 v0 = make_uint4(0u, 0u, 0u, 0u);
            uint4 v1 = make_uint4(0u, 0u, 0u, 0u);
            if (gr < N_NODES) { v0 = __ldg(srcp); v1 = __ldg(srcp + 1); }
            char* row = sAh + arow * A_STRIDE + ahalf * 32;
            *((uint4*)(row + 0))  = v0;
            *((uint4*)(row + 16)) = v1;
        } else {
            const float4* srcp = (const float4*)((const float*)xin +
                                                 (size_t)gr * 128 + k0 + ahalf * 16);
#pragma unroll
            for (int j = 0; j < 4; j++) {
                float4 v = make_float4(0.f, 0.f, 0.f, 0.f);
                if (gr < N_NODES) v = __ldg(srcp + j);
                __nv_bfloat16 h0 = __float2bfloat16(v.x);
                __nv_bfloat16 h1 = __float2bfloat16(v.y);
                __nv_bfloat16 h2 = __float2bfloat16(v.z);
                __nv_bfloat16 h3 = __float2bfloat16(v.w);
                uint2 hp, lp;
                hp.x = (uint32_t)__bfloat16_as_ushort(h0) |
                       ((uint32_t)__bfloat16_as_ushort(h1) << 16);
                hp.y = (uint32_t)__bfloat16_as_ushort(h2) |
                       ((uint32_t)__bfloat16_as_ushort(h3) << 16);
                lp.x = pack_bf16(v.x - __bfloat162float(h0), v.y - __bfloat162float(h1));
                lp.y = pack_bf16(v.z - __bfloat162float(h2), v.w - __bfloat162float(h3));
                int off = arow * A_STRIDE + (ahalf * 16 + j * 4) * 2;
                *((uint2*)(sAh + off)) = hp;
                *((uint2*)(sAl + off)) = lp;
            }
        }
        // ---- load W chunk: 128 n-rows x 32 k bf16, hi (t<128) / lo (t>=128)
        {
            int n = t & 127;
            const __nv_bfloat16* wsrc =
                fh ? ((t < 128) ? WlTh : WlTl) : ((t < 128) ? WrTh : WrTl);
            char* wdst = (t < 128) ? sWh : sWl;
            const uint4* src16 = (const uint4*)(wsrc + n * 128 + k0);
            uint4 v0 = __ldg(src16 + 0);
            uint4 v1 = __ldg(src16 + 1);
            uint4 v2 = __ldg(src16 + 2);
            uint4 v3 = __ldg(src16 + 3);
            char* row = wdst + n * A_STRIDE;
            *((uint4*)(row + 0))  = v0;
            *((uint4*)(row + 16)) = v1;
            *((uint4*)(row + 32)) = v2;
            *((uint4*)(row + 48)) = v3;
        }
        __syncthreads();

        // ---- compute: 2 k16-steps
#pragma unroll
        for (int kk = 0; kk < 2; kk++) {
            const int kb = kk * 32;
            uint32_t ah[4][4], al[4][4];
#pragma unroll
            for (int mi = 0; mi < 4; mi++) {
                int rb = warpM * 64 + mi * 16;
                int r1 = (rb + grp) * A_STRIDE + kb + tig * 4;
                int r2 = (rb + grp + 8) * A_STRIDE + kb + tig * 4;
                ah[mi][0] = *((uint32_t*)(sAh + r1));
                ah[mi][1] = *((uint32_t*)(sAh + r2));
                ah[mi][2] = *((uint32_t*)(sAh + r1 + 16));
                ah[mi][3] = *((uint32_t*)(sAh + r2 + 16));
                if (useAl) {
                    al[mi][0] = *((uint32_t*)(sAl + r1));
                    al[mi][1] = *((uint32_t*)(sAl + r2));
                    al[mi][2] = *((uint32_t*)(sAl + r1 + 16));
                    al[mi][3] = *((uint32_t*)(sAl + r2 + 16));
                }
            }
#pragma unroll
            for (int ni = 0; ni < 4; ni++) {
                int nrow = warpN * 32 + ni * 8 + grp;
                int wo = nrow * A_STRIDE + kb + tig * 4;
                uint32_t wh0 = *((uint32_t*)(sWh + wo));
                uint32_t wh1 = *((uint32_t*)(sWh + wo + 16));
                uint32_t wl0 = *((uint32_t*)(sWl + wo));
                uint32_t wl1 = *((uint32_t*)(sWl + wo + 16));
#pragma unroll
                for (int mi = 0; mi < 4; mi++) {
                    mma_bf16(acc[mi][ni], ah[mi], wh0, wh1);
                    mma_bf16(acc[mi][ni], ah[mi], wl0, wl1);
                    if (useAl) mma_bf16(acc[mi][ni], al[mi], wh0, wh1);
                }
            }
        }
        __syncthreads();
    }

    // ---- epilogue: bias + relu, bf16 stores
#pragma unroll
    for (int mi = 0; mi < 4; mi++) {
        int r1 = m0 + warpM * 64 + mi * 16 + grp;
        int r2 = r1 + 8;
#pragma unroll
        for (int ni = 0; ni < 4; ni++) {
            int col = warpN * 32 + ni * 8 + tig * 2;
            float b0 = __ldg(&bias[col]);
            float b1 = __ldg(&bias[col + 1]);
            if (r1 < N_NODES) {
                __nv_bfloat162 v = __floats2bfloat162_rn(
                    fmaxf(acc[mi][ni][0] + b0, 0.f),
                    fmaxf(acc[mi][ni][1] + b1, 0.f));
                *((__nv_bfloat162*)(out + (size_t)r1 * 128 + col)) = v;
            }
            if (r2 < N_NODES) {
                __nv_bfloat162 v = __floats2bfloat162_rn(
                    fmaxf(acc[mi][ni][2] + b0, 0.f),
                    fmaxf(acc[mi][ni][3] + b1, 0.f));
                *((__nv_bfloat162*)(out + (size_t)r2 * 128 + col)) = v;
            }
        }
    }
}

// ===========================================================================
__global__ void pool_kernel(const __nv_bfloat16* __restrict__ h,
                            float* __restrict__ pool) {
    __shared__ float4 s[256];
    int t = threadIdx.x;
    int c = t & 31;
    int rlane = t >> 5;
    float4 acc = make_float4(0.f, 0.f, 0.f, 0.f);
    const uint2* h2 = (const uint2*)h;
    for (int r = blockIdx.x * 8 + rlane; r < N_NODES; r += gridDim.x * 8) {
        float4 v = bf4_to_f4(__ldg(h2 + (size_t)r * 32 + c));
        acc.x += v.x; acc.y += v.y; acc.z += v.z; acc.w += v.w;
    }
    s[t] = acc;
    __syncthreads();
    if (rlane == 0) {
#pragma unroll
        for (int i = 1; i < 8; i++) {
            float4 v = s[i * 32 + c];
            acc.x += v.x; acc.y += v.y; acc.z += v.z; acc.w += v.w;
        }
        atomicAdd(&pool[c * 4 + 0], acc.x);
        atomicAdd(&pool[c * 4 + 1], acc.y);
        atomicAdd(&pool[c * 4 + 2], acc.z);
        atomicAdd(&pool[c * 4 + 3], acc.w);
    }
}

__global__ void head_kernel(const float* __restrict__ pool,
                            const float* __restrict__ Wg,
                            const float* __restrict__ bg,
                            float* __restrict__ out) {
    int j = threadIdx.x;
    if (j >= D_LAT) return;
    float acc = bg[j];
    const float invn = 1.0f / (float)N_NODES;
#pragma unroll 8
    for (int k = 0; k < D; k++)
        acc += (pool[k] * invn) * Wg[k * D_LAT + j];
    out[j] = 1.0f / (1.0f + expf(-acc));
}

// ===========================================================================
extern "C" void kernel_launch(void* const* d_in, const int* in_sizes, int n_in,
                              void* d_out, int out_size) {
    const float* x   = (const float*)d_in[0];
    const int*   ei  = (const int*)d_in[1];
    const float* b1  = (const float*)d_in[4];
    const float* b2  = (const float*)d_in[7];
    const float* b3  = (const float*)d_in[10];
    const float* Wg  = (const float*)d_in[11];
    const float* bg  = (const float*)d_in[12];
    float* out = (float*)d_out;

    const int* src = ei;
    const int* dst = ei + N_EDGES;

    float *pool;
    __nv_bfloat16 *aggr, *hA, *hB, *wh, *wl;
    int *deg, *offs, *cursor, *part, *perm;
    cudaGetSymbolAddress((void**)&aggr,   g_aggr);
    cudaGetSymbolAddress((void**)&hA,     g_hA);
    cudaGetSymbolAddress((void**)&hB,     g_hB);
    cudaGetSymbolAddress((void**)&pool,   g_pool);
    cudaGetSymbolAddress((void**)&deg,    g_deg);
    cudaGetSymbolAddress((void**)&offs,   g_offs);
    cudaGetSymbolAddress((void**)&cursor, g_cursor);
    cudaGetSymbolAddress((void**)&part,   g_part);
    cudaGetSymbolAddress((void**)&perm,   g_perm);
    cudaGetSymbolAddress((void**)&wh,     g_wh);
    cudaGetSymbolAddress((void**)&wl,     g_wl);

    const int gemm_blocks = (N_NODES + 127) / 128;      // 782
    const int aggr_blocks = (N_NODES + 7) / 8;          // 12500
    const int edge_blocks = (N_EDGES + 255) / 256;

    // --- weight prep (single launch for all 6 matrices) ---
    prep_w6_kernel<<<(6 * 16384 + 255) / 256, 256>>>(
        (const float*)d_in[2], (const float*)d_in[3],
        (const float*)d_in[5], (const float*)d_in[6],
        (const float*)d_in[8], (const float*)d_in[9], wh, wl);
#define WTH(m) (wh + (size_t)(m) * 16384)
#define WTL(m) (wl + (size_t)(m) * 16384)

    // --- CSR-by-dst build (once, reused by all 3 layers) ---
    zero_i_kernel<<<SCAN_BLOCKS, 256>>>(deg, N_NODES);
    count_kernel<<<edge_blocks, 256>>>(dst, deg);
    scan1_kernel<<<SCAN_BLOCKS, 256>>>(deg, offs, part);
    scan2_kernel<<<1, 512>>>(part);
    scan3_kernel<<<SCAN_BLOCKS, 256>>>(offs, part, cursor);
    permute_kernel<<<edge_blocks, 256>>>(src, dst, cursor, perm);

    // --- layer 1: x (fp32) -> hA (bf16) ---
    gather_aggr_t<false><<<aggr_blocks, 256>>>(x, perm, offs, deg, aggr);
    sage_gemm_mma_t<false><<<gemm_blocks, 256>>>(
        aggr, x, WTH(0), WTL(0), WTH(1), WTL(1), b1, hA);

    // --- layer 2: hA (bf16) -> hB (bf16) ---
    gather_aggr_t<true><<<aggr_blocks, 256>>>(hA, perm, offs, deg, aggr);
    sage_gemm_mma_t<true><<<gemm_blocks, 256>>>(
        aggr, hA, WTH(2), WTL(2), WTH(3), WTL(3), b2, hB);

    // --- layer 3: hB (bf16) -> hA (bf16) ---
    gather_aggr_t<true><<<aggr_blocks, 256>>>(hB, perm, offs, deg, aggr);
    sage_gemm_mma_t<true><<<gemm_blocks, 256>>>(
        aggr, hB, WTH(4), WTL(4), WTH(5), WTL(5), b3, hA);

    // --- pool + head ---
    zero_f_kernel<<<1, 128>>>(pool, D);
    pool_kernel<<<256, 256>>>(hA, pool);
    head_kernel<<<1, 64>>>(pool, Wg, bg, out);
}

// round 11
// speedup vs baseline: 1.0257x; 1.0257x over previous
#include <cuda_runtime.h>
#include <cuda_bf16.h>
#include <math.h>
#include <cstdint>

#define N_NODES 100000
#define D 128
#define D_LAT 64
#define N_EDGES 1600000
#define SCAN_BLOCKS ((N_NODES + 255) / 256)   // 391

// Scratch (device globals: allocation-free, graph-capture safe)
__device__ __nv_bfloat16  g_aggr[(size_t)N_NODES * D];
__device__ __nv_bfloat16  g_hA[(size_t)N_NODES * D];
__device__ __nv_bfloat16  g_hB[(size_t)N_NODES * D];
__device__ float g_pool[D];
__device__ int   g_deg[N_NODES];
__device__ int   g_offs[N_NODES];
__device__ int   g_cursor[N_NODES];
__device__ int   g_part[SCAN_BLOCKS];
__device__ int   g_perm[N_EDGES];
// transposed weights, bf16 hi/lo split: [mat 0..5][n*128+k]
__device__ __nv_bfloat16 g_wh[6 * 128 * 128];
__device__ __nv_bfloat16 g_wl[6 * 128 * 128];

// ===========================================================================
__device__ __forceinline__ float4 bf4_to_f4(uint2 u) {
    __nv_bfloat162 a = *reinterpret_cast<__nv_bfloat162*>(&u.x);
    __nv_bfloat162 b = *reinterpret_cast<__nv_bfloat162*>(&u.y);
    float2 fa = __bfloat1622float2(a);
    float2 fb = __bfloat1622float2(b);
    return make_float4(fa.x, fa.y, fb.x, fb.y);
}
__device__ __forceinline__ __nv_bfloat162 as_bf2(uint32_t u) {
    return *reinterpret_cast<__nv_bfloat162*>(&u);
}
__device__ __forceinline__ uint32_t pack_bf16(float a, float b) {
    __nv_bfloat16 ha = __float2bfloat16(a);
    __nv_bfloat16 hb = __float2bfloat16(b);
    return (uint32_t)__bfloat16_as_ushort(ha) |
           ((uint32_t)__bfloat16_as_ushort(hb) << 16);
}

// ===========================================================================
// small utility kernels
// ===========================================================================
__global__ void zero_i_kernel(int* __restrict__ p, int n) {
    int i = blockIdx.x * blockDim.x + threadIdx.x;
    if (i < n) p[i] = 0;
}
__global__ void zero_f_kernel(float* __restrict__ p, int n) {
    int i = blockIdx.x * blockDim.x + threadIdx.x;
    if (i < n) p[i] = 0.f;
}
__global__ void count_kernel(const int* __restrict__ dst, int* __restrict__ deg) {
    int e = blockIdx.x * blockDim.x + threadIdx.x;
    if (e < N_EDGES) atomicAdd(&deg[dst[e]], 1);
}
__global__ void scan1_kernel(const int* __restrict__ deg,
                             int* __restrict__ offs, int* __restrict__ part) {
    __shared__ int s[256];
    int t = threadIdx.x;
    int i = blockIdx.x * 256 + t;
    int v = (i < N_NODES) ? deg[i] : 0;
    s[t] = v;
    __syncthreads();
#pragma unroll
    for (int d = 1; d < 256; d <<= 1) {
        int u = (t >= d) ? s[t - d] : 0;
        __syncthreads();
        s[t] += u;
        __syncthreads();
    }
    if (i < N_NODES) offs[i] = s[t] - v;
    if (t == 255) part[blockIdx.x] = s[255];
}
__global__ void scan2_kernel(int* __restrict__ part) {
    __shared__ int s[512];
    int t = threadIdx.x;
    int v = (t < SCAN_BLOCKS) ? part[t] : 0;
    s[t] = v;
    __syncthreads();
#pragma unroll
    for (int d = 1; d < 512; d <<= 1) {
        int u = (t >= d) ? s[t - d] : 0;
        __syncthreads();
        s[t] += u;
        __syncthreads();
    }
    if (t < SCAN_BLOCKS) part[t] = s[t] - v;
}
__global__ void scan3_kernel(int* __restrict__ offs, const int* __restrict__ part,
                             int* __restrict__ cursor) {
    int i = blockIdx.x * blockDim.x + threadIdx.x;
    if (i < N_NODES) {
        int o = offs[i] + part[i >> 8];
        offs[i] = o;
        cursor[i] = o;
    }
}
__global__ void permute_kernel(const int* __restrict__ src, const int* __restrict__ dst,
                               int* __restrict__ cursor, int* __restrict__ perm) {
    int e = blockIdx.x * blockDim.x + threadIdx.x;
    if (e < N_EDGES) {
        int pos = atomicAdd(&cursor[dst[e]], 1);
        perm[pos] = src[e];
    }
}
__global__ void prep_w6_kernel(const float* __restrict__ W0, const float* __restrict__ W1,
                               const float* __restrict__ W2, const float* __restrict__ W3,
                               const float* __restrict__ W4, const float* __restrict__ W5,
                               __nv_bfloat16* __restrict__ Th,
                               __nv_bfloat16* __restrict__ Tl) {
    int t = blockIdx.x * 256 + threadIdx.x;
    if (t >= 6 * 16384) return;
    int m = t >> 14, i = t & 16383;
    const float* W = (m == 0) ? W0 : (m == 1) ? W1 : (m == 2) ? W2
                   : (m == 3) ? W3 : (m == 4) ? W4 : W5;
    int n = i >> 7, k = i & 127;
    float w = W[k * 128 + n];
    __nv_bfloat16 h = __float2bfloat16(w);
    Th[t] = h;
    Tl[t] = __float2bfloat16(w - __bfloat162float(h));
}

// ===========================================================================
// gather-based mean aggregation: one warp per node, unroll 8.
// bf16 inputs (layers 2/3, post-relu => non-negative): pairwise HADD2 tree
// over the 8 rows, fp32 accumulation only of per-iteration partials.
// fp32 inputs (layer 1, signed): exact fp32 adds.
// ===========================================================================
template<bool BF16IN>
__global__ __launch_bounds__(256) void gather_aggr_t(
    const void* __restrict__ xv, const int* __restrict__ perm,
    const int* __restrict__ offs, const int* __restrict__ deg,
    __nv_bfloat16* __restrict__ aggr)
{
    int warp = (blockIdx.x * blockDim.x + threadIdx.x) >> 5;
    int lane = threadIdx.x & 31;
    if (warp >= N_NODES) return;
    int beg = __ldg(&offs[warp]);
    int cnt = __ldg(&deg[warp]);
    int end = beg + cnt;

    const uint2*  x2 = (const uint2*)xv;
    const float4* x4 = (const float4*)xv;

    float4 acc = make_float4(0.f, 0.f, 0.f, 0.f);
    int e = beg;
    for (; e + 8 <= end; e += 8) {
        int s0 = __ldg(&perm[e + 0]);
        int s1 = __ldg(&perm[e + 1]);
        int s2 = __ldg(&perm[e + 2]);
        int s3 = __ldg(&perm[e + 3]);
        int s4 = __ldg(&perm[e + 4]);
        int s5 = __ldg(&perm[e + 5]);
        int s6 = __ldg(&perm[e + 6]);
        int s7 = __ldg(&perm[e + 7]);
        if (BF16IN) {
            uint2 u0 = __ldg(x2 + (size_t)s0 * 32 + lane);
            uint2 u1 = __ldg(x2 + (size_t)s1 * 32 + lane);
            uint2 u2 = __ldg(x2 + (size_t)s2 * 32 + lane);
            uint2 u3 = __ldg(x2 + (size_t)s3 * 32 + lane);
            uint2 u4 = __ldg(x2 + (size_t)s4 * 32 + lane);
            uint2 u5 = __ldg(x2 + (size_t)s5 * 32 + lane);
            uint2 u6 = __ldg(x2 + (size_t)s6 * 32 + lane);
            uint2 u7 = __ldg(x2 + (size_t)s7 * 32 + lane);
            // component .x -> features (4l, 4l+1); component .y -> (4l+2, 4l+3)
            __nv_bfloat162 px = __hadd2(
                __hadd2(__hadd2(as_bf2(u0.x), as_bf2(u1.x)),
                        __hadd2(as_bf2(u2.x), as_bf2(u3.x))),
                __hadd2(__hadd2(as_bf2(u4.x), as_bf2(u5.x)),
                        __hadd2(as_bf2(u6.x), as_bf2(u7.x))));
            __nv_bfloat162 py = __hadd2(
                __hadd2(__hadd2(as_bf2(u0.y), as_bf2(u1.y)),
                        __hadd2(as_bf2(u2.y), as_bf2(u3.y))),
                __hadd2(__hadd2(as_bf2(u4.y), as_bf2(u5.y)),
                        __hadd2(as_bf2(u6.y), as_bf2(u7.y))));
            float2 fx = __bfloat1622float2(px);
            float2 fy = __bfloat1622float2(py);
            acc.x += fx.x; acc.y += fx.y;
            acc.z += fy.x; acc.w += fy.y;
        } else {
            float4 v0 = __ldg(x4 + (size_t)s0 * 32 + lane);
            float4 v1 = __ldg(x4 + (size_t)s1 * 32 + lane);
            float4 v2 = __ldg(x4 + (size_t)s2 * 32 + lane);
            float4 v3 = __ldg(x4 + (size_t)s3 * 32 + lane);
            float4 v4 = __ldg(x4 + (size_t)s4 * 32 + lane);
            float4 v5 = __ldg(x4 + (size_t)s5 * 32 + lane);
            float4 v6 = __ldg(x4 + (size_t)s6 * 32 + lane);
            float4 v7 = __ldg(x4 + (size_t)s7 * 32 + lane);
            acc.x += ((v0.x + v1.x) + (v2.x + v3.x)) + ((v4.x + v5.x) + (v6.x + v7.x));
            acc.y += ((v0.y + v1.y) + (v2.y + v3.y)) + ((v4.y + v5.y) + (v6.y + v7.y));
            acc.z += ((v0.z + v1.z) + (v2.z + v3.z)) + ((v4.z + v5.z) + (v6.z + v7.z));
            acc.w += ((v0.w + v1.w) + (v2.w + v3.w)) + ((v4.w + v5.w) + (v6.w + v7.w));
        }
    }
    for (; e < end; e++) {
        int s0 = __ldg(&perm[e]);
        float4 v0 = BF16IN ? bf4_to_f4(__ldg(x2 + (size_t)s0 * 32 + lane))
                           : __ldg(x4 + (size_t)s0 * 32 + lane);
        acc.x += v0.x; acc.y += v0.y; acc.z += v0.z; acc.w += v0.w;
    }
    float sc = (cnt > 0) ? (1.0f / (float)cnt) : 0.0f;
    uint2 o;
    o.x = pack_bf16(acc.x * sc, acc.y * sc);
    o.y = pack_bf16(acc.z * sc, acc.w * sc);
    ((uint2*)aggr)[(size_t)warp * 32 + lane] = o;
}

// ===========================================================================
// bf16 mma.sync fused SAGE layer:
//   out_bf16 = relu( aggr @ Wl + xin @ Wr + b )
// A-side single bf16 (2 MMAs vs W hi/lo); fp32 xin (layer 1) gets hi/lo
// split (3 MMAs). W always hi/lo. CTA 128x128, warp 64x32, K=256 in 8x32.
// ===========================================================================
#define A_STRIDE 80   // 16B-aligned; bank = (grp*20 + tig) mod 32 -> conflict-free
#define TILE_BYTES (128 * A_STRIDE)  // 10240

__device__ __forceinline__ void mma_bf16(float* c, const uint32_t* a,
                                         uint32_t b0, uint32_t b1) {
    asm volatile(
        "mma.sync.aligned.m16n8k16.row.col.f32.bf16.bf16.f32 "
        "{%0,%1,%2,%3}, {%4,%5,%6,%7}, {%8,%9}, {%0,%1,%2,%3};\n"
        : "+f"(c[0]), "+f"(c[1]), "+f"(c[2]), "+f"(c[3])
        : "r"(a[0]), "r"(a[1]), "r"(a[2]), "r"(a[3]), "r"(b0), "r"(b1));
}

template<bool BF16IN>
__global__ __launch_bounds__(256, 2) void sage_gemm_mma_t(
    const __nv_bfloat16* __restrict__ aggr, const void* __restrict__ xin,
    const __nv_bfloat16* __restrict__ WlTh, const __nv_bfloat16* __restrict__ WlTl,
    const __nv_bfloat16* __restrict__ WrTh, const __nv_bfloat16* __restrict__ WrTl,
    const float* __restrict__ bias, __nv_bfloat16* __restrict__ out)
{
    __shared__ char sAh[TILE_BYTES];
    __shared__ char sAl[TILE_BYTES];   // only used for fp32 xin (layer 1)
    __shared__ char sWh[TILE_BYTES];
    __shared__ char sWl[TILE_BYTES];

    const int t    = threadIdx.x;
    const int wid  = t >> 5;
    const int lane = t & 31;
    const int grp  = lane >> 2;
    const int tig  = lane & 3;
    const int warpM = wid >> 2;
    const int warpN = wid & 3;
    const int m0 = blockIdx.x * 128;

    float acc[4][4][4];
#pragma unroll
    for (int i = 0; i < 4; i++)
#pragma unroll
        for (int j = 0; j < 4; j++)
#pragma unroll
            for (int r = 0; r < 4; r++) acc[i][j][r] = 0.f;

    const int arow  = t >> 1;
    const int ahalf = t & 1;
    const int gr = m0 + arow;

    for (int c = 0; c < 8; c++) {
        const bool fh = (c < 4);          // aggregation half of K
        const int k0 = (c & 3) * 32;
        const bool useAl = !fh && !BF16IN;

        // ---- load A chunk: rows 128 x 32 k
        if (fh || BF16IN) {
            const __nv_bfloat16* srcb = fh ? aggr : (const __nv_bfloat16*)xin;
            const uint4* srcp = (const uint4*)(srcb + (size_t)gr * 128 + k0 + ahalf * 16);
            uint4 v0 = make_uint4(0u, 0u, 0u, 0u);
            uint4 v1 = make_uint4(0u, 0u, 0u, 0u);
            if (gr < N_NODES) { v0 = __ldg(srcp); v1 = __ldg(srcp + 1); }
            char* row = sAh + arow * A_STRIDE + ahalf * 32;
            *((uint4*)(row + 0))  = v0;
            *((uint4*)(row + 16)) = v1;
        } else {
            const float4* srcp = (const float4*)((const float*)xin +
                                                 (size_t)gr * 128 + k0 + ahalf * 16);
#pragma unroll
            for (int j = 0; j < 4; j++) {
                float4 v = make_float4(0.f, 0.f, 0.f, 0.f);
                if (gr < N_NODES) v = __ldg(srcp + j);
                __nv_bfloat16 h0 = __float2bfloat16(v.x);
                __nv_bfloat16 h1 = __float2bfloat16(v.y);
                __nv_bfloat16 h2 = __float2bfloat16(v.z);
                __nv_bfloat16 h3 = __float2bfloat16(v.w);
                uint2 hp, lp;
                hp.x = (uint32_t)__bfloat16_as_ushort(h0) |
                       ((uint32_t)__bfloat16_as_ushort(h1) << 16);
                hp.y = (uint32_t)__bfloat16_as_ushort(h2) |
                       ((uint32_t)__bfloat16_as_ushort(h3) << 16);
                lp.x = pack_bf16(v.x - __bfloat162float(h0), v.y - __bfloat162float(h1));
                lp.y = pack_bf16(v.z - __bfloat162float(h2), v.w - __bfloat162float(h3));
                int off = arow * A_STRIDE + (ahalf * 16 + j * 4) * 2;
                *((uint2*)(sAh + off)) = hp;
                *((uint2*)(sAl + off)) = lp;
            }
        }
        // ---- load W chunk: 128 n-rows x 32 k bf16, hi (t<128) / lo (t>=128)
        {
            int n = t & 127;
            const __nv_bfloat16* wsrc =
                fh ? ((t < 128) ? WlTh : WlTl) : ((t < 128) ? WrTh : WrTl);
            char* wdst = (t < 128) ? sWh : sWl;
            const uint4* src16 = (const uint4*)(wsrc + n * 128 + k0);
            uint4 v0 = __ldg(src16 + 0);
            uint4 v1 = __ldg(src16 + 1);
            uint4 v2 = __ldg(src16 + 2);
            uint4 v3 = __ldg(src16 + 3);
            char* row = wdst + n * A_STRIDE;
            *((uint4*)(row + 0))  = v0;
            *((uint4*)(row + 16)) = v1;
            *((uint4*)(row + 32)) = v2;
            *((uint4*)(row + 48)) = v3;
        }
        __syncthreads();

        // ---- compute: 2 k16-steps
#pragma unroll
        for (int kk = 0; kk < 2; kk++) {
            const int kb = kk * 32;
            uint32_t ah[4][4], al[4][4];
#pragma unroll
            for (int mi = 0; mi < 4; mi++) {
                int rb = warpM * 64 + mi * 16;
                int r1 = (rb + grp) * A_STRIDE + kb + tig * 4;
                int r2 = (rb + grp + 8) * A_STRIDE + kb + tig * 4;
                ah[mi][0] = *((uint32_t*)(sAh + r1));
                ah[mi][1] = *((uint32_t*)(sAh + r2));
                ah[mi][2] = *((uint32_t*)(sAh + r1 + 16));
                ah[mi][3] = *((uint32_t*)(sAh + r2 + 16));
                if (useAl) {
                    al[mi][0] = *((uint32_t*)(sAl + r1));
                    al[mi][1] = *((uint32_t*)(sAl + r2));
                    al[mi][2] = *((uint32_t*)(sAl + r1 + 16));
                    al[mi][3] = *((uint32_t*)(sAl + r2 + 16));
                }
            }
#pragma unroll
            for (int ni = 0; ni < 4; ni++) {
                int nrow = warpN * 32 + ni * 8 + grp;
                int wo = nrow * A_STRIDE + kb + tig * 4;
                uint32_t wh0 = *((uint32_t*)(sWh + wo));
                uint32_t wh1 = *((uint32_t*)(sWh + wo + 16));
                uint32_t wl0 = *((uint32_t*)(sWl + wo));
                uint32_t wl1 = *((uint32_t*)(sWl + wo + 16));
#pragma unroll
                for (int mi = 0; mi < 4; mi++) {
                    mma_bf16(acc[mi][ni], ah[mi], wh0, wh1);
                    mma_bf16(acc[mi][ni], ah[mi], wl0, wl1);
                    if (useAl) mma_bf16(acc[mi][ni], al[mi], wh0, wh1);
                }
            }
        }
        __syncthreads();
    }

    // ---- epilogue: bias + relu, bf16 stores
#pragma unroll
    for (int mi = 0; mi < 4; mi++) {
        int r1 = m0 + warpM * 64 + mi * 16 + grp;
        int r2 = r1 + 8;
#pragma unroll
        for (int ni = 0; ni < 4; ni++) {
            int col = warpN * 32 + ni * 8 + tig * 2;
            float b0 = __ldg(&bias[col]);
            float b1 = __ldg(&bias[col + 1]);
            if (r1 < N_NODES) {
                __nv_bfloat162 v = __floats2bfloat162_rn(
                    fmaxf(acc[mi][ni][0] + b0, 0.f),
                    fmaxf(acc[mi][ni][1] + b1, 0.f));
                *((__nv_bfloat162*)(out + (size_t)r1 * 128 + col)) = v;
            }
            if (r2 < N_NODES) {
                __nv_bfloat162 v = __floats2bfloat162_rn(
                    fmaxf(acc[mi][ni][2] + b0, 0.f),
                    fmaxf(acc[mi][ni][3] + b1, 0.f));
                *((__nv_bfloat162*)(out + (size_t)r2 * 128 + col)) = v;
            }
        }
    }
}

// ===========================================================================
__global__ void pool_kernel(const __nv_bfloat16* __restrict__ h,
                            float* __restrict__ pool) {
    __shared__ float4 s[256];
    int t = threadIdx.x;
    int c = t & 31;
    int rlane = t >> 5;
    float4 acc = make_float4(0.f, 0.f, 0.f, 0.f);
    const uint2* h2 = (const uint2*)h;
    for (int r = blockIdx.x * 8 + rlane; r < N_NODES; r += gridDim.x * 8) {
        float4 v = bf4_to_f4(__ldg(h2 + (size_t)r * 32 + c));
        acc.x += v.x; acc.y += v.y; acc.z += v.z; acc.w += v.w;
    }
    s[t] = acc;
    __syncthreads();
    if (rlane == 0) {
#pragma unroll
        for (int i = 1; i < 8; i++) {
            float4 v = s[i * 32 + c];
            acc.x += v.x; acc.y += v.y; acc.z += v.z; acc.w += v.w;
        }
        atomicAdd(&pool[c * 4 + 0], acc.x);
        atomicAdd(&pool[c * 4 + 1], acc.y);
        atomicAdd(&pool[c * 4 + 2], acc.z);
        atomicAdd(&pool[c * 4 + 3], acc.w);
    }
}

__global__ void head_kernel(const float* __restrict__ pool,
                            const float* __restrict__ Wg,
                            const float* __restrict__ bg,
                            float* __restrict__ out) {
    int j = threadIdx.x;
    if (j >= D_LAT) return;
    float acc = bg[j];
    const float invn = 1.0f / (float)N_NODES;
#pragma unroll 8
    for (int k = 0; k < D; k++)
        acc += (pool[k] * invn) * Wg[k * D_LAT + j];
    out[j] = 1.0f / (1.0f + expf(-acc));
}

// ===========================================================================
extern "C" void kernel_launch(void* const* d_in, const int* in_sizes, int n_in,
                              void* d_out, int out_size) {
    const float* x   = (const float*)d_in[0];
    const int*   ei  = (const int*)d_in[1];
    const float* b1  = (const float*)d_in[4];
    const float* b2  = (const float*)d_in[7];
    const float* b3  = (const float*)d_in[10];
    const float* Wg  = (const float*)d_in[11];
    const float* bg  = (const float*)d_in[12];
    float* out = (float*)d_out;

    const int* src = ei;
    const int* dst = ei + N_EDGES;

    float *pool;
    __nv_bfloat16 *aggr, *hA, *hB, *wh, *wl;
    int *deg, *offs, *cursor, *part, *perm;
    cudaGetSymbolAddress((void**)&aggr,   g_aggr);
    cudaGetSymbolAddress((void**)&hA,     g_hA);
    cudaGetSymbolAddress((void**)&hB,     g_hB);
    cudaGetSymbolAddress((void**)&pool,   g_pool);
    cudaGetSymbolAddress((void**)&deg,    g_deg);
    cudaGetSymbolAddress((void**)&offs,   g_offs);
    cudaGetSymbolAddress((void**)&cursor, g_cursor);
    cudaGetSymbolAddress((void**)&part,   g_part);
    cudaGetSymbolAddress((void**)&perm,   g_perm);
    cudaGetSymbolAddress((void**)&wh,     g_wh);
    cudaGetSymbolAddress((void**)&wl,     g_wl);

    const int gemm_blocks = (N_NODES + 127) / 128;      // 782
    const int aggr_blocks = (N_NODES + 7) / 8;          // 12500
    const int edge_blocks = (N_EDGES + 255) / 256;

    // --- weight prep (single launch for all 6 matrices) ---
    prep_w6_kernel<<<(6 * 16384 + 255) / 256, 256>>>(
        (const float*)d_in[2], (const float*)d_in[3],
        (const float*)d_in[5], (const float*)d_in[6],
        (const float*)d_in[8], (const float*)d_in[9], wh, wl);
#define WTH(m) (wh + (size_t)(m) * 16384)
#define WTL(m) (wl + (size_t)(m) * 16384)

    // --- CSR-by-dst build (once, reused by all 3 layers) ---
    zero_i_kernel<<<SCAN_BLOCKS, 256>>>(deg, N_NODES);
    count_kernel<<<edge_blocks, 256>>>(dst, deg);
    scan1_kernel<<<SCAN_BLOCKS, 256>>>(deg, offs, part);
    scan2_kernel<<<1, 512>>>(part);
    scan3_kernel<<<SCAN_BLOCKS, 256>>>(offs, part, cursor);
    permute_kernel<<<edge_blocks, 256>>>(src, dst, cursor, perm);

    // --- layer 1: x (fp32) -> hA (bf16) ---
    gather_aggr_t<false><<<aggr_blocks, 256>>>(x, perm, offs, deg, aggr);
    sage_gemm_mma_t<false><<<gemm_blocks, 256>>>(
        aggr, x, WTH(0), WTL(0), WTH(1), WTL(1), b1, hA);

    // --- layer 2: hA (bf16) -> hB (bf16) ---
    gather_aggr_t<true><<<aggr_blocks, 256>>>(hA, perm, offs, deg, aggr);
    sage_gemm_mma_t<true><<<gemm_blocks, 256>>>(
        aggr, hA, WTH(2), WTL(2), WTH(3), WTL(3), b2, hB);

    // --- layer 3: hB (bf16) -> hA (bf16) ---
    gather_aggr_t<true><<<aggr_blocks, 256>>>(hB, perm, offs, deg, aggr);
    sage_gemm_mma_t<true><<<gemm_blocks, 256>>>(
        aggr, hB, WTH(4), WTL(4), WTH(5), WTL(5), b3, hA);

    // --- pool + head ---
    zero_f_kernel<<<1, 128>>>(pool, D);
    pool_kernel<<<256, 256>>>(hA, pool);
    head_kernel<<<1, 64>>>(pool, Wg, bg, out);
}

// round 12
// speedup vs baseline: 1.1234x; 1.0952x over previous
#include <cuda_runtime.h>
#include <cuda_bf16.h>
#include <math.h>
#include <cstdint>

#define N_NODES 100000
#define D 128
#define D_LAT 64
#define N_EDGES 1600000
#define SCAN_BLOCKS ((N_NODES + 255) / 256)   // 391

// Scratch (device globals: allocation-free, graph-capture safe)
__device__ __nv_bfloat16  g_xbf[(size_t)N_NODES * D];
__device__ __nv_bfloat16  g_aggr[(size_t)N_NODES * D];
__device__ __nv_bfloat16  g_hA[(size_t)N_NODES * D];
__device__ __nv_bfloat16  g_hB[(size_t)N_NODES * D];
__device__ float g_pool[D];
__device__ int   g_deg[N_NODES];
__device__ int   g_offs[N_NODES];
__device__ int   g_cursor[N_NODES];
__device__ int   g_part[SCAN_BLOCKS];
__device__ int   g_perm[N_EDGES];
// transposed weights, bf16 hi/lo split: [mat 0..5][n*128+k]
__device__ __nv_bfloat16 g_wh[6 * 128 * 128];
__device__ __nv_bfloat16 g_wl[6 * 128 * 128];

// ===========================================================================
__device__ __forceinline__ float4 bf4_to_f4(uint2 u) {
    __nv_bfloat162 a = *reinterpret_cast<__nv_bfloat162*>(&u.x);
    __nv_bfloat162 b = *reinterpret_cast<__nv_bfloat162*>(&u.y);
    float2 fa = __bfloat1622float2(a);
    float2 fb = __bfloat1622float2(b);
    return make_float4(fa.x, fa.y, fb.x, fb.y);
}
__device__ __forceinline__ __nv_bfloat162 as_bf2(uint32_t u) {
    return *reinterpret_cast<__nv_bfloat162*>(&u);
}
__device__ __forceinline__ uint32_t pack_bf16(float a, float b) {
    __nv_bfloat16 ha = __float2bfloat16(a);
    __nv_bfloat16 hb = __float2bfloat16(b);
    return (uint32_t)__bfloat16_as_ushort(ha) |
           ((uint32_t)__bfloat16_as_ushort(hb) << 16);
}

// ===========================================================================
// small utility kernels
// ===========================================================================
__global__ void zero_i_kernel(int* __restrict__ p, int n) {
    int i = blockIdx.x * blockDim.x + threadIdx.x;
    if (i < n) p[i] = 0;
}
__global__ void zero_f_kernel(float* __restrict__ p, int n) {
    int i = blockIdx.x * blockDim.x + threadIdx.x;
    if (i < n) p[i] = 0.f;
}
// fp32 -> bf16 feature conversion (x), 4 elems/thread
__global__ void conv_x_kernel(const float4* __restrict__ x4,
                              uint2* __restrict__ xb, int n4) {
    int i = blockIdx.x * blockDim.x + threadIdx.x;
    if (i < n4) {
        float4 v = __ldg(x4 + i);
        uint2 o;
        o.x = pack_bf16(v.x, v.y);
        o.y = pack_bf16(v.z, v.w);
        xb[i] = o;
    }
}
__global__ void count_kernel(const int* __restrict__ dst, int* __restrict__ deg) {
    int e = blockIdx.x * blockDim.x + threadIdx.x;
    if (e < N_EDGES) atomicAdd(&deg[dst[e]], 1);
}
__global__ void scan1_kernel(const int* __restrict__ deg,
                             int* __restrict__ offs, int* __restrict__ part) {
    __shared__ int s[256];
    int t = threadIdx.x;
    int i = blockIdx.x * 256 + t;
    int v = (i < N_NODES) ? deg[i] : 0;
    s[t] = v;
    __syncthreads();
#pragma unroll
    for (int d = 1; d < 256; d <<= 1) {
        int u = (t >= d) ? s[t - d] : 0;
        __syncthreads();
        s[t] += u;
        __syncthreads();
    }
    if (i < N_NODES) offs[i] = s[t] - v;
    if (t == 255) part[blockIdx.x] = s[255];
}
__global__ void scan2_kernel(int* __restrict__ part) {
    __shared__ int s[512];
    int t = threadIdx.x;
    int v = (t < SCAN_BLOCKS) ? part[t] : 0;
    s[t] = v;
    __syncthreads();
#pragma unroll
    for (int d = 1; d < 512; d <<= 1) {
        int u = (t >= d) ? s[t - d] : 0;
        __syncthreads();
        s[t] += u;
        __syncthreads();
    }
    if (t < SCAN_BLOCKS) part[t] = s[t] - v;
}
__global__ void scan3_kernel(int* __restrict__ offs, const int* __restrict__ part,
                             int* __restrict__ cursor) {
    int i = blockIdx.x * blockDim.x + threadIdx.x;
    if (i < N_NODES) {
        int o = offs[i] + part[i >> 8];
        offs[i] = o;
        cursor[i] = o;
    }
}
__global__ void permute_kernel(const int* __restrict__ src, const int* __restrict__ dst,
                               int* __restrict__ cursor, int* __restrict__ perm) {
    int e = blockIdx.x * blockDim.x + threadIdx.x;
    if (e < N_EDGES) {
        int pos = atomicAdd(&cursor[dst[e]], 1);
        perm[pos] = src[e];
    }
}
__global__ void prep_w6_kernel(const float* __restrict__ W0, const float* __restrict__ W1,
                               const float* __restrict__ W2, const float* __restrict__ W3,
                               const float* __restrict__ W4, const float* __restrict__ W5,
                               __nv_bfloat16* __restrict__ Th,
                               __nv_bfloat16* __restrict__ Tl) {
    int t = blockIdx.x * 256 + threadIdx.x;
    if (t >= 6 * 16384) return;
    int m = t >> 14, i = t & 16383;
    const float* W = (m == 0) ? W0 : (m == 1) ? W1 : (m == 2) ? W2
                   : (m == 3) ? W3 : (m == 4) ? W4 : W5;
    int n = i >> 7, k = i & 127;
    float w = W[k * 128 + n];
    __nv_bfloat16 h = __float2bfloat16(w);
    Th[t] = h;
    Tl[t] = __float2bfloat16(w - __bfloat162float(h));
}

// ===========================================================================
// gather-based mean aggregation: one warp per node, unroll 8,
// pairwise HADD2 tree over the 8 rows, fp32 accumulation of partials.
// ===========================================================================
__global__ __launch_bounds__(256) void gather_aggr(
    const __nv_bfloat16* __restrict__ xv, const int* __restrict__ perm,
    const int* __restrict__ offs, const int* __restrict__ deg,
    __nv_bfloat16* __restrict__ aggr)
{
    int warp = (blockIdx.x * blockDim.x + threadIdx.x) >> 5;
    int lane = threadIdx.x & 31;
    if (warp >= N_NODES) return;
    int beg = __ldg(&offs[warp]);
    int cnt = __ldg(&deg[warp]);
    int end = beg + cnt;

    const uint2* x2 = (const uint2*)xv;

    float4 acc = make_float4(0.f, 0.f, 0.f, 0.f);
    int e = beg;
    for (; e + 8 <= end; e += 8) {
        int s0 = __ldg(&perm[e + 0]);
        int s1 = __ldg(&perm[e + 1]);
        int s2 = __ldg(&perm[e + 2]);
        int s3 = __ldg(&perm[e + 3]);
        int s4 = __ldg(&perm[e + 4]);
        int s5 = __ldg(&perm[e + 5]);
        int s6 = __ldg(&perm[e + 6]);
        int s7 = __ldg(&perm[e + 7]);
        uint2 u0 = __ldg(x2 + (size_t)s0 * 32 + lane);
        uint2 u1 = __ldg(x2 + (size_t)s1 * 32 + lane);
        uint2 u2 = __ldg(x2 + (size_t)s2 * 32 + lane);
        uint2 u3 = __ldg(x2 + (size_t)s3 * 32 + lane);
        uint2 u4 = __ldg(x2 + (size_t)s4 * 32 + lane);
        uint2 u5 = __ldg(x2 + (size_t)s5 * 32 + lane);
        uint2 u6 = __ldg(x2 + (size_t)s6 * 32 + lane);
        uint2 u7 = __ldg(x2 + (size_t)s7 * 32 + lane);
        __nv_bfloat162 px = __hadd2(
            __hadd2(__hadd2(as_bf2(u0.x), as_bf2(u1.x)),
                    __hadd2(as_bf2(u2.x), as_bf2(u3.x))),
            __hadd2(__hadd2(as_bf2(u4.x), as_bf2(u5.x)),
                    __hadd2(as_bf2(u6.x), as_bf2(u7.x))));
        __nv_bfloat162 py = __hadd2(
            __hadd2(__hadd2(as_bf2(u0.y), as_bf2(u1.y)),
                    __hadd2(as_bf2(u2.y), as_bf2(u3.y))),
            __hadd2(__hadd2(as_bf2(u4.y), as_bf2(u5.y)),
                    __hadd2(as_bf2(u6.y), as_bf2(u7.y))));
        float2 fx = __bfloat1622float2(px);
        float2 fy = __bfloat1622float2(py);
        acc.x += fx.x; acc.y += fx.y;
        acc.z += fy.x; acc.w += fy.y;
    }
    for (; e < end; e++) {
        int s0 = __ldg(&perm[e]);
        float4 v0 = bf4_to_f4(__ldg(x2 + (size_t)s0 * 32 + lane));
        acc.x += v0.x; acc.y += v0.y; acc.z += v0.z; acc.w += v0.w;
    }
    float sc = (cnt > 0) ? (1.0f / (float)cnt) : 0.0f;
    uint2 o;
    o.x = pack_bf16(acc.x * sc, acc.y * sc);
    o.y = pack_bf16(acc.z * sc, acc.w * sc);
    ((uint2*)aggr)[(size_t)warp * 32 + lane] = o;
}

// ===========================================================================
// bf16 mma.sync fused SAGE layer (all inputs bf16):
//   out_bf16 = relu( aggr @ Wl + xin @ Wr + b )
// A-side single bf16 (2 MMAs vs W hi/lo); W always hi/lo (systematic error).
// CTA 128x128, warp 64x32, K=256 in 8 chunks of 32.
// ===========================================================================
#define A_STRIDE 80   // 16B-aligned; bank = (grp*20 + tig) mod 32 -> conflict-free
#define TILE_BYTES (128 * A_STRIDE)  // 10240

__device__ __forceinline__ void mma_bf16(float* c, const uint32_t* a,
                                         uint32_t b0, uint32_t b1) {
    asm volatile(
        "mma.sync.aligned.m16n8k16.row.col.f32.bf16.bf16.f32 "
        "{%0,%1,%2,%3}, {%4,%5,%6,%7}, {%8,%9}, {%0,%1,%2,%3};\n"
        : "+f"(c[0]), "+f"(c[1]), "+f"(c[2]), "+f"(c[3])
        : "r"(a[0]), "r"(a[1]), "r"(a[2]), "r"(a[3]), "r"(b0), "r"(b1));
}

__global__ __launch_bounds__(256, 2) void sage_gemm_mma(
    const __nv_bfloat16* __restrict__ aggr, const __nv_bfloat16* __restrict__ xin,
    const __nv_bfloat16* __restrict__ WlTh, const __nv_bfloat16* __restrict__ WlTl,
    const __nv_bfloat16* __restrict__ WrTh, const __nv_bfloat16* __restrict__ WrTl,
    const float* __restrict__ bias, __nv_bfloat16* __restrict__ out)
{
    __shared__ char sAh[TILE_BYTES];
    __shared__ char sWh[TILE_BYTES];
    __shared__ char sWl[TILE_BYTES];

    const int t    = threadIdx.x;
    const int wid  = t >> 5;
    const int lane = t & 31;
    const int grp  = lane >> 2;
    const int tig  = lane & 3;
    const int warpM = wid >> 2;
    const int warpN = wid & 3;
    const int m0 = blockIdx.x * 128;

    float acc[4][4][4];
#pragma unroll
    for (int i = 0; i < 4; i++)
#pragma unroll
        for (int j = 0; j < 4; j++)
#pragma unroll
            for (int r = 0; r < 4; r++) acc[i][j][r] = 0.f;

    const int arow  = t >> 1;
    const int ahalf = t & 1;
    const int gr = m0 + arow;

    for (int c = 0; c < 8; c++) {
        const bool fh = (c < 4);          // aggregation half of K
        const int k0 = (c & 3) * 32;

        // ---- load A chunk (bf16 straight copy): rows 128 x 32 k
        {
            const __nv_bfloat16* srcb = fh ? aggr : xin;
            const uint4* srcp = (const uint4*)(srcb + (size_t)gr * 128 + k0 + ahalf * 16);
            uint4 v0 = make_uint4(0u, 0u, 0u, 0u);
            uint4 v1 = make_uint4(0u, 0u, 0u, 0u);
            if (gr < N_NODES) { v0 = __ldg(srcp); v1 = __ldg(srcp + 1); }
            char* row = sAh + arow * A_STRIDE + ahalf * 32;
            *((uint4*)(row + 0))  = v0;
            *((uint4*)(row + 16)) = v1;
        }
        // ---- load W chunk: 128 n-rows x 32 k bf16, hi (t<128) / lo (t>=128)
        {
            int n = t & 127;
            const __nv_bfloat16* wsrc =
                fh ? ((t < 128) ? WlTh : WlTl) : ((t < 128) ? WrTh : WrTl);
            char* wdst = (t < 128) ? sWh : sWl;
            const uint4* src16 = (const uint4*)(wsrc + n * 128 + k0);
            uint4 v0 = __ldg(src16 + 0);
            uint4 v1 = __ldg(src16 + 1);
            uint4 v2 = __ldg(src16 + 2);
            uint4 v3 = __ldg(src16 + 3);
            char* row = wdst + n * A_STRIDE;
            *((uint4*)(row + 0))  = v0;
            *((uint4*)(row + 16)) = v1;
            *((uint4*)(row + 32)) = v2;
            *((uint4*)(row + 48)) = v3;
        }
        __syncthreads();

        // ---- compute: 2 k16-steps
#pragma unroll
        for (int kk = 0; kk < 2; kk++) {
            const int kb = kk * 32;
            uint32_t ah[4][4];
#pragma unroll
            for (int mi = 0; mi < 4; mi++) {
                int rb = warpM * 64 + mi * 16;
                int r1 = (rb + grp) * A_STRIDE + kb + tig * 4;
                int r2 = (rb + grp + 8) * A_STRIDE + kb + tig * 4;
                ah[mi][0] = *((uint32_t*)(sAh + r1));
                ah[mi][1] = *((uint32_t*)(sAh + r2));
                ah[mi][2] = *((uint32_t*)(sAh + r1 + 16));
                ah[mi][3] = *((uint32_t*)(sAh + r2 + 16));
            }
#pragma unroll
            for (int ni = 0; ni < 4; ni++) {
                int nrow = warpN * 32 + ni * 8 + grp;
                int wo = nrow * A_STRIDE + kb + tig * 4;
                uint32_t wh0 = *((uint32_t*)(sWh + wo));
                uint32_t wh1 = *((uint32_t*)(sWh + wo + 16));
                uint32_t wl0 = *((uint32_t*)(sWl + wo));
                uint32_t wl1 = *((uint32_t*)(sWl + wo + 16));
#pragma unroll
                for (int mi = 0; mi < 4; mi++) {
                    mma_bf16(acc[mi][ni], ah[mi], wh0, wh1);
                    mma_bf16(acc[mi][ni], ah[mi], wl0, wl1);
                }
            }
        }
        __syncthreads();
    }

    // ---- epilogue: bias + relu, bf16 stores
#pragma unroll
    for (int mi = 0; mi < 4; mi++) {
        int r1 = m0 + warpM * 64 + mi * 16 + grp;
        int r2 = r1 + 8;
#pragma unroll
        for (int ni = 0; ni < 4; ni++) {
            int col = warpN * 32 + ni * 8 + tig * 2;
            float b0 = __ldg(&bias[col]);
            float b1 = __ldg(&bias[col + 1]);
            if (r1 < N_NODES) {
                __nv_bfloat162 v = __floats2bfloat162_rn(
                    fmaxf(acc[mi][ni][0] + b0, 0.f),
                    fmaxf(acc[mi][ni][1] + b1, 0.f));
                *((__nv_bfloat162*)(out + (size_t)r1 * 128 + col)) = v;
            }
            if (r2 < N_NODES) {
                __nv_bfloat162 v = __floats2bfloat162_rn(
                    fmaxf(acc[mi][ni][2] + b0, 0.f),
                    fmaxf(acc[mi][ni][3] + b1, 0.f));
                *((__nv_bfloat162*)(out + (size_t)r2 * 128 + col)) = v;
            }
        }
    }
}

// ===========================================================================
__global__ void pool_kernel(const __nv_bfloat16* __restrict__ h,
                            float* __restrict__ pool) {
    __shared__ float4 s[256];
    int t = threadIdx.x;
    int c = t & 31;
    int rlane = t >> 5;
    float4 acc = make_float4(0.f, 0.f, 0.f, 0.f);
    const uint2* h2 = (const uint2*)h;
    for (int r = blockIdx.x * 8 + rlane; r < N_NODES; r += gridDim.x * 8) {
        float4 v = bf4_to_f4(__ldg(h2 + (size_t)r * 32 + c));
        acc.x += v.x; acc.y += v.y; acc.z += v.z; acc.w += v.w;
    }
    s[t] = acc;
    __syncthreads();
    if (rlane == 0) {
#pragma unroll
        for (int i = 1; i < 8; i++) {
            float4 v = s[i * 32 + c];
            acc.x += v.x; acc.y += v.y; acc.z += v.z; acc.w += v.w;
        }
        atomicAdd(&pool[c * 4 + 0], acc.x);
        atomicAdd(&pool[c * 4 + 1], acc.y);
        atomicAdd(&pool[c * 4 + 2], acc.z);
        atomicAdd(&pool[c * 4 + 3], acc.w);
    }
}

__global__ void head_kernel(const float* __restrict__ pool,
                            const float* __restrict__ Wg,
                            const float* __restrict__ bg,
                            float* __restrict__ out) {
    int j = threadIdx.x;
    if (j >= D_LAT) return;
    float acc = bg[j];
    const float invn = 1.0f / (float)N_NODES;
#pragma unroll 8
    for (int k = 0; k < D; k++)
        acc += (pool[k] * invn) * Wg[k * D_LAT + j];
    out[j] = 1.0f / (1.0f + expf(-acc));
}

// ===========================================================================
extern "C" void kernel_launch(void* const* d_in, const int* in_sizes, int n_in,
                              void* d_out, int out_size) {
    const float* x   = (const float*)d_in[0];
    const int*   ei  = (const int*)d_in[1];
    const float* b1  = (const float*)d_in[4];
    const float* b2  = (const float*)d_in[7];
    const float* b3  = (const float*)d_in[10];
    const float* Wg  = (const float*)d_in[11];
    const float* bg  = (const float*)d_in[12];
    float* out = (float*)d_out;

    const int* src = ei;
    const int* dst = ei + N_EDGES;

    float *pool;
    __nv_bfloat16 *xbf, *aggr, *hA, *hB, *wh, *wl;
    int *deg, *offs, *cursor, *part, *perm;
    cudaGetSymbolAddress((void**)&xbf,    g_xbf);
    cudaGetSymbolAddress((void**)&aggr,   g_aggr);
    cudaGetSymbolAddress((void**)&hA,     g_hA);
    cudaGetSymbolAddress((void**)&hB,     g_hB);
    cudaGetSymbolAddress((void**)&pool,   g_pool);
    cudaGetSymbolAddress((void**)&deg,    g_deg);
    cudaGetSymbolAddress((void**)&offs,   g_offs);
    cudaGetSymbolAddress((void**)&cursor, g_cursor);
    cudaGetSymbolAddress((void**)&part,   g_part);
    cudaGetSymbolAddress((void**)&perm,   g_perm);
    cudaGetSymbolAddress((void**)&wh,     g_wh);
    cudaGetSymbolAddress((void**)&wl,     g_wl);

    const int gemm_blocks = (N_NODES + 127) / 128;      // 782
    const int aggr_blocks = (N_NODES + 7) / 8;          // 12500
    const int edge_blocks = (N_EDGES + 255) / 256;
    const int feat4 = N_NODES * D / 4;                  // 3.2M

    // --- weight prep + x -> bf16 conversion ---
    prep_w6_kernel<<<(6 * 16384 + 255) / 256, 256>>>(
        (const float*)d_in[2], (const float*)d_in[3],
        (const float*)d_in[5], (const float*)d_in[6],
        (const float*)d_in[8], (const float*)d_in[9], wh, wl);
    conv_x_kernel<<<(feat4 + 255) / 256, 256>>>((const float4*)x, (uint2*)xbf, feat4);
#define WTH(m) (wh + (size_t)(m) * 16384)
#define WTL(m) (wl + (size_t)(m) * 16384)

    // --- CSR-by-dst build (once, reused by all 3 layers) ---
    zero_i_kernel<<<SCAN_BLOCKS, 256>>>(deg, N_NODES);
    count_kernel<<<edge_blocks, 256>>>(dst, deg);
    scan1_kernel<<<SCAN_BLOCKS, 256>>>(deg, offs, part);
    scan2_kernel<<<1, 512>>>(part);
    scan3_kernel<<<SCAN_BLOCKS, 256>>>(offs, part, cursor);
    permute_kernel<<<edge_blocks, 256>>>(src, dst, cursor, perm);

    // --- layer 1: xbf (bf16) -> hA (bf16) ---
    gather_aggr<<<aggr_blocks, 256>>>(xbf, perm, offs, deg, aggr);
    sage_gemm_mma<<<gemm_blocks, 256>>>(
        aggr, xbf, WTH(0), WTL(0), WTH(1), WTL(1), b1, hA);

    // --- layer 2: hA -> hB ---
    gather_aggr<<<aggr_blocks, 256>>>(hA, perm, offs, deg, aggr);
    sage_gemm_mma<<<gemm_blocks, 256>>>(
        aggr, hA, WTH(2), WTL(2), WTH(3), WTL(3), b2, hB);

    // --- layer 3: hB -> hA ---
    gather_aggr<<<aggr_blocks, 256>>>(hB, perm, offs, deg, aggr);
    sage_gemm_mma<<<gemm_blocks, 256>>>(
        aggr, hB, WTH(4), WTL(4), WTH(5), WTL(5), b3, hA);

    // --- pool + head ---
    zero_f_kernel<<<1, 128>>>(pool, D);
    pool_kernel<<<256, 256>>>(hA, pool);
    head_kernel<<<1, 64>>>(pool, Wg, bg, out);
}